// round 7
// baseline (speedup 1.0000x reference)
#include <cuda_runtime.h>

// GraphConv: out = (feat + scatter_sum(feat[src]*norm_l[src] -> dst)) * norm_r
// norm_l = rsqrt(max(out_deg,1)+1), norm_r = rsqrt(max(in_deg,1)+1)
// N=100000 nodes, D=64 f32 features, E=1.25M edges.
// NOTE: JAX default config downcasts jnp.int64 -> int32, so src/dst are int32.

#define N_MAX 100000
#define D 64

__device__ float g_outdeg[N_MAX];
__device__ float g_indeg[N_MAX];
__device__ float g_norml[N_MAX];
__device__ float g_normr[N_MAX];

// ---------------------------------------------------------------------------
// 1) zero the output accumulator (poisoned 0xAA by harness) + degree scratch
// ---------------------------------------------------------------------------
__global__ void k_zero(float* __restrict__ out, int total_out, int n) {
    int stride = gridDim.x * blockDim.x;
    int i = blockIdx.x * blockDim.x + threadIdx.x;
    float4* o4 = reinterpret_cast<float4*>(out);
    int total4 = total_out >> 2;
    const float4 z4 = make_float4(0.f, 0.f, 0.f, 0.f);
    for (int j = i; j < total4; j += stride) o4[j] = z4;
    for (int j = i; j < n; j += stride) {
        g_outdeg[j] = 0.f;
        g_indeg[j]  = 0.f;
    }
}

// ---------------------------------------------------------------------------
// 2) degree counting (no-return atomics -> REDG)
// ---------------------------------------------------------------------------
__global__ void k_degree(const int* __restrict__ src,
                         const int* __restrict__ dst, int E) {
    int i = blockIdx.x * blockDim.x + threadIdx.x;
    if (i < E) {
        atomicAdd(&g_outdeg[src[i]], 1.0f);
        atomicAdd(&g_indeg[dst[i]], 1.0f);
    }
}

// ---------------------------------------------------------------------------
// 3) normalization factors
// ---------------------------------------------------------------------------
__global__ void k_norm(int n) {
    int i = blockIdx.x * blockDim.x + threadIdx.x;
    if (i < n) {
        g_norml[i] = rsqrtf(fmaxf(g_outdeg[i], 1.0f) + 1.0f);
        g_normr[i] = rsqrtf(fmaxf(g_indeg[i], 1.0f) + 1.0f);
    }
}

// ---------------------------------------------------------------------------
// 4) edge scatter: 16 lanes per edge (2 edges/warp); each lane gathers one
//    float4 of feat[src] (coalesced, L2-resident), scales by norm_l[src],
//    and issues a single vector reduction atomicAdd(float4*) -> REDG.128.
//    20M vector REDs instead of 80M scalar ones.
// ---------------------------------------------------------------------------
__global__ void k_scatter(const float* __restrict__ feat,
                          const int* __restrict__ src,
                          const int* __restrict__ dst,
                          float* __restrict__ out, int E) {
    int gt   = blockIdx.x * blockDim.x + threadIdx.x;
    int edge = gt >> 4;                 // 16 lanes per edge
    int lane = gt & 15;
    if (edge >= E) return;

    int s = __ldg(&src[edge]);          // same addr across the 16 lanes
    int d = __ldg(&dst[edge]);
    float nl = __ldg(&g_norml[s]);

    float4 v = *reinterpret_cast<const float4*>(feat + ((long)s << 6) + (lane << 2));
    v.x *= nl; v.y *= nl; v.z *= nl; v.w *= nl;

    float4* o = reinterpret_cast<float4*>(out + ((long)d << 6) + (lane << 2));
    atomicAdd(o, v);                    // sm_90+: red.global.v4.f32.add
}

// ---------------------------------------------------------------------------
// 5) finalize: out = (feat + h_neigh) * norm_r, float4-vectorized
// ---------------------------------------------------------------------------
__global__ void k_final(const float* __restrict__ feat,
                        float* __restrict__ out, int n) {
    int i = blockIdx.x * blockDim.x + threadIdx.x;   // one float4 per thread
    int total4 = n * (D / 4);                        // n * 16
    if (i < total4) {
        int node = i >> 4;                           // 16 float4 per node
        float nr = g_normr[node];
        float4 f = reinterpret_cast<const float4*>(feat)[i];
        float4 h = reinterpret_cast<float4*>(out)[i];
        float4 r;
        r.x = (f.x + h.x) * nr;
        r.y = (f.y + h.y) * nr;
        r.z = (f.z + h.z) * nr;
        r.w = (f.w + h.w) * nr;
        reinterpret_cast<float4*>(out)[i] = r;
    }
}

extern "C" void kernel_launch(void* const* d_in, const int* in_sizes, int n_in,
                              void* d_out, int out_size) {
    const float* feat = (const float*)d_in[0];
    const int*   src  = (const int*)d_in[1];
    const int*   dst  = (const int*)d_in[2];
    float*       out  = (float*)d_out;

    int n = in_sizes[0] / D;      // 100000
    int E = in_sizes[1];          // 1250000

    // 1) zero accumulator + degree scratch
    k_zero<<<2048, 256>>>(out, n * D, n);

    // 2) degrees
    k_degree<<<(E + 255) / 256, 256>>>(src, dst, E);

    // 3) norms
    k_norm<<<(n + 255) / 256, 256>>>(n);

    // 4) scatter: 16 threads per edge
    {
        long long threads = (long long)E * 16;
        int blocks = (int)((threads + 255) / 256);
        k_scatter<<<blocks, 256>>>(feat, src, dst, out, E);
    }

    // 5) finalize
    {
        int total4 = n * (D / 4);
        k_final<<<(total4 + 255) / 256, 256>>>(feat, out, n);
    }
}